// round 1
// baseline (speedup 1.0000x reference)
#include <cuda_runtime.h>

#define BETA 0.95f
#define NSTEPS 25

__global__ __launch_bounds__(256)
void Net_91164975824989_kernel(
    const float* __restrict__ x,
    const float* __restrict__ W1, const float* __restrict__ b1,
    const float* __restrict__ W2, const float* __restrict__ b2,
    const float* __restrict__ W3, const float* __restrict__ b3,
    const float* __restrict__ W4, const float* __restrict__ b4,
    float* __restrict__ out, int B)
{
    __shared__ float  h1s[8][30];
    __shared__ float  h2s[8][30];
    __shared__ float2 tab[8];

    const int tid  = threadIdx.x;
    const int p    = tid >> 5;   // pattern 0..7 (warps 0..7)
    const int lane = tid & 31;

    const int b = blockIdx.x * blockDim.x + tid;
    const bool active = (b < B);

    // ---- start input loads early (overlap with table preamble) ----
    float v[9];
    #pragma unroll
    for (int j = 0; j < 9; j++)
        v[j] = active ? __ldg(&x[b * 9 + j]) : 0.0f;

    // ---- preamble: build the 8-entry line->softmax table ----
    // Layer 1: h1 = relu(W1 @ s + b1), s = 3-bit pattern bits
    if (p < 8 && lane < 30) {
        float s0 = (float)( p       & 1);
        float s1 = (float)((p >> 1) & 1);
        float s2 = (float)((p >> 2) & 1);
        float a = b1[lane]
                + W1[lane * 3 + 0] * s0
                + W1[lane * 3 + 1] * s1
                + W1[lane * 3 + 2] * s2;
        h1s[p][lane] = fmaxf(a, 0.0f);
    }
    __syncthreads();

    // Layer 2: 30x30
    if (p < 8 && lane < 30) {
        float a = b2[lane];
        #pragma unroll
        for (int g = 0; g < 30; g++)
            a += W2[lane * 30 + g] * h1s[p][g];
        h2s[p][lane] = fmaxf(a, 0.0f);
    }
    __syncthreads();

    // Layers 3,4 + softmax: one thread per pattern (tiny)
    if (p < 8 && lane == 0) {
        float h3[3];
        #pragma unroll
        for (int o = 0; o < 3; o++) {
            float a = b3[o];
            #pragma unroll
            for (int g = 0; g < 30; g++)
                a += W3[o * 30 + g] * h2s[p][g];
            h3[o] = fmaxf(a, 0.0f);
        }
        float o0 = fmaxf(b4[0] + W4[0] * h3[0] + W4[1] * h3[1] + W4[2] * h3[2], 0.0f);
        float o1 = fmaxf(b4[1] + W4[3] * h3[0] + W4[4] * h3[1] + W4[5] * h3[2], 0.0f);
        float m  = fmaxf(o0, o1);
        float e0 = expf(o0 - m);
        float e1 = expf(o1 - m);
        float inv = 1.0f / (e0 + e1);
        tab[p] = make_float2(e0 * inv, e1 * inv);
    }
    __syncthreads();

    // ---- main: LIF dynamics + table-lookup accumulation ----
    float mem[9], rst[9];
    #pragma unroll
    for (int j = 0; j < 9; j++) { mem[j] = 0.0f; rst[j] = 0.0f; }

    float accx = 0.0f, accy = 0.0f;

    #pragma unroll
    for (int t = 0; t < NSTEPS; t++) {
        unsigned s = 0u;
        #pragma unroll
        for (int j = 0; j < 9; j++) {
            // mem_new = BETA*mem + v - reset  (reset = previous spike)
            mem[j] = BETA * mem[j] + v[j] - rst[j];
            bool sp = mem[j] > 1.0f;
            rst[j] = sp ? 1.0f : 0.0f;
            s |= ((unsigned)sp) << j;
        }
        // rows: bits (0,1,2) (3,4,5) (6,7,8); cols: (0,3,6) (1,4,7) (2,5,8)
        int r0 =  s        & 7;
        int r1 = (s >> 3)  & 7;
        int r2 = (s >> 6)  & 7;
        int c0 = ( s       & 1) | ((s >> 2) & 2) | ((s >> 4) & 4);
        int c1 = ((s >> 1) & 1) | ((s >> 3) & 2) | ((s >> 5) & 4);
        int c2 = ((s >> 2) & 1) | ((s >> 4) & 2) | ((s >> 6) & 4);

        float2 a0 = tab[r0], a1 = tab[r1], a2 = tab[r2];
        float2 a3 = tab[c0], a4 = tab[c1], a5 = tab[c2];
        accx += a0.x + a1.x + a2.x + a3.x + a4.x + a5.x;
        accy += a0.y + a1.y + a2.y + a3.y + a4.y + a5.y;
    }

    if (active) {
        reinterpret_cast<float2*>(out)[b] = make_float2(accx, accy);
    }
}

extern "C" void kernel_launch(void* const* d_in, const int* in_sizes, int n_in,
                              void* d_out, int out_size) {
    const float* x  = (const float*)d_in[0];
    const float* W1 = (const float*)d_in[1];
    const float* b1 = (const float*)d_in[2];
    const float* W2 = (const float*)d_in[3];
    const float* b2 = (const float*)d_in[4];
    const float* W3 = (const float*)d_in[5];
    const float* b3 = (const float*)d_in[6];
    const float* W4 = (const float*)d_in[7];
    const float* b4 = (const float*)d_in[8];
    float* out = (float*)d_out;

    int B = in_sizes[0] / 9;
    int threads = 256;
    int blocks = (B + threads - 1) / threads;

    Net_91164975824989_kernel<<<blocks, threads>>>(
        x, W1, b1, W2, b2, W3, b3, W4, b4, out, B);
}

// round 2
// speedup vs baseline: 1.0520x; 1.0520x over previous
#include <cuda_runtime.h>

#define BETA 0.95f
#define NSTEPS 25

__global__ __launch_bounds__(128)
void Net_91164975824989_kernel(
    const float* __restrict__ x,
    const float* __restrict__ W1, const float* __restrict__ b1,
    const float* __restrict__ W2, const float* __restrict__ b2,
    const float* __restrict__ W3, const float* __restrict__ b3,
    const float* __restrict__ W4, const float* __restrict__ b4,
    float* __restrict__ out, int B)
{
    __shared__ float h1s[8][30];
    __shared__ float h2s[8][30];
    __shared__ float Tx[8];   // tab[p].x (softmax prob 0 for pattern p)
    __shared__ float cf[8];   // multilinear coefficients

    const int tid = threadIdx.x;
    const int b   = blockIdx.x * blockDim.x + tid;
    const bool active = (b < B);

    // ---- issue input loads early (overlap DRAM latency with preamble) ----
    float v[9];
    #pragma unroll
    for (int j = 0; j < 9; j++)
        v[j] = active ? __ldg(&x[b * 9 + j]) : 0.0f;

    // ================= preamble: 8-entry table -> multilinear coeffs ======
    const int pp = tid >> 4;   // pattern 0..7
    const int nn = tid & 15;   // neuron base; handles nn and nn+16

    {   // Layer 1: h1 = relu(W1 @ bits(p) + b1)
        float s0 = (float)( pp       & 1);
        float s1 = (float)((pp >> 1) & 1);
        float s2 = (float)((pp >> 2) & 1);
        {
            float a = b1[nn] + W1[nn*3+0]*s0 + W1[nn*3+1]*s1 + W1[nn*3+2]*s2;
            h1s[pp][nn] = fmaxf(a, 0.0f);
        }
        int n2 = nn + 16;
        if (n2 < 30) {
            float a = b1[n2] + W1[n2*3+0]*s0 + W1[n2*3+1]*s1 + W1[n2*3+2]*s2;
            h1s[pp][n2] = fmaxf(a, 0.0f);
        }
    }
    __syncthreads();

    {   // Layer 2: 30x30
        {
            float a = b2[nn];
            #pragma unroll
            for (int g = 0; g < 30; g++) a += W2[nn*30+g] * h1s[pp][g];
            h2s[pp][nn] = fmaxf(a, 0.0f);
        }
        int n2 = nn + 16;
        if (n2 < 30) {
            float a = b2[n2];
            #pragma unroll
            for (int g = 0; g < 30; g++) a += W2[n2*30+g] * h1s[pp][g];
            h2s[pp][n2] = fmaxf(a, 0.0f);
        }
    }
    __syncthreads();

    if (tid < 8) {   // Layers 3,4 + softmax -> Tx[p]
        int p = tid;
        float h3[3];
        #pragma unroll
        for (int o = 0; o < 3; o++) {
            float a = b3[o];
            #pragma unroll
            for (int g = 0; g < 30; g++) a += W3[o*30+g] * h2s[p][g];
            h3[o] = fmaxf(a, 0.0f);
        }
        float o0 = fmaxf(b4[0] + W4[0]*h3[0] + W4[1]*h3[1] + W4[2]*h3[2], 0.0f);
        float o1 = fmaxf(b4[1] + W4[3]*h3[0] + W4[4]*h3[1] + W4[5]*h3[2], 0.0f);
        float m  = fmaxf(o0, o1);
        float e0 = expf(o0 - m);
        float e1 = expf(o1 - m);
        Tx[p] = e0 / (e0 + e1);
    }
    __syncthreads();

    if (tid == 0) {  // multilinear coefficients over (b0,b1,b2); index = b0|b1<<1|b2<<2
        float t0=Tx[0], t1=Tx[1], t2=Tx[2], t3=Tx[3];
        float t4=Tx[4], t5=Tx[5], t6=Tx[6], t7=Tx[7];
        cf[0] = t0;                       // const
        cf[1] = t1 - t0;                  // A
        cf[2] = t2 - t0;                  // B
        cf[3] = t4 - t0;                  // C
        cf[4] = t3 - t1 - t2 + t0;        // AB
        cf[5] = t5 - t1 - t4 + t0;        // AC
        cf[6] = t6 - t2 - t4 + t0;        // BC
        cf[7] = t7 - t3 - t5 - t6 + t1 + t2 + t4 - t0;  // ABC
    }
    __syncthreads();

    const float c0 = cf[0], cA = cf[1], cB = cf[2], cC = cf[3];
    const float cAB = cf[4], cAC = cf[5], cBC = cf[6], cABC = cf[7];

    // ================= LIF dynamics: build 25-bit spike trains ============
    float mem[9];
    unsigned st[9];
    bool sp[9];
    #pragma unroll
    for (int j = 0; j < 9; j++) { mem[j] = 0.0f; st[j] = 0u; sp[j] = false; }

    #pragma unroll
    for (int t = 0; t < NSTEPS; t++) {
        #pragma unroll
        for (int j = 0; j < 9; j++) {
            // mem_new = BETA*mem + v - [prev spike]
            float m = fmaf(BETA, mem[j], v[j]);
            if (sp[j]) m -= 1.0f;
            mem[j] = m;
            bool s = m > 1.0f;
            if (s) st[j] |= (1u << t);
            sp[j] = s;
        }
    }

    // ================= popcount epilogue ==================================
    // Lines: rows r -> neurons (3r,3r+1,3r+2) at positions (A,B,C)
    //        cols c -> neurons (c, c+3, c+6) at positions (A,B,C)
    float accx = 150.0f * c0;   // 25 steps x 6 lines

    // single terms: neuron j appears at position (j%3) in its row, (j/3) in its col
    {
        const float s1c[3] = { cA, cB, cC };
        #pragma unroll
        for (int j = 0; j < 9; j++) {
            float w = s1c[j % 3] + s1c[j / 3];
            accx = fmaf(w, (float)__popc(st[j]), accx);
        }
    }
    // pair + triple terms, rows
    #pragma unroll
    for (int r = 0; r < 3; r++) {
        unsigned a = st[3*r], bb = st[3*r+1], c = st[3*r+2];
        unsigned ab = a & bb;
        accx = fmaf(cAB,  (float)__popc(ab),     accx);
        accx = fmaf(cAC,  (float)__popc(a & c),  accx);
        accx = fmaf(cBC,  (float)__popc(bb & c), accx);
        accx = fmaf(cABC, (float)__popc(ab & c), accx);
    }
    // pair + triple terms, cols
    #pragma unroll
    for (int c2 = 0; c2 < 3; c2++) {
        unsigned a = st[c2], bb = st[c2+3], c = st[c2+6];
        unsigned ab = a & bb;
        accx = fmaf(cAB,  (float)__popc(ab),     accx);
        accx = fmaf(cAC,  (float)__popc(a & c),  accx);
        accx = fmaf(cBC,  (float)__popc(bb & c), accx);
        accx = fmaf(cABC, (float)__popc(ab & c), accx);
    }

    if (active) {
        reinterpret_cast<float2*>(out)[b] = make_float2(accx, 150.0f - accx);
    }
}

extern "C" void kernel_launch(void* const* d_in, const int* in_sizes, int n_in,
                              void* d_out, int out_size) {
    const float* x  = (const float*)d_in[0];
    const float* W1 = (const float*)d_in[1];
    const float* b1 = (const float*)d_in[2];
    const float* W2 = (const float*)d_in[3];
    const float* b2 = (const float*)d_in[4];
    const float* W3 = (const float*)d_in[5];
    const float* b3 = (const float*)d_in[6];
    const float* W4 = (const float*)d_in[7];
    const float* b4 = (const float*)d_in[8];
    float* out = (float*)d_out;

    int B = in_sizes[0] / 9;
    int threads = 128;
    int blocks = (B + threads - 1) / threads;

    Net_91164975824989_kernel<<<blocks, threads>>>(
        x, W1, b1, W2, b2, W3, b3, W4, b4, out, B);
}